// round 3
// baseline (speedup 1.0000x reference)
#include <cuda_runtime.h>
#include <cuda_bf16.h>
#include <mma.h>
#include <math.h>

using namespace nvcuda;

// Problem constants
#define BATCH 2
#define SEQ   2048
#define EMB   1024
#define HEADS 16
#define HDIM  64
#define ROWS  (BATCH * SEQ)   // 4096

// -------------------- scratch (allocation-free: device globals) --------------------
__device__ float g_Q[ROWS * EMB];
__device__ float g_K[ROWS * EMB];
__device__ float g_V[ROWS * EMB];
__device__ float g_O[ROWS * EMB];

__device__ __forceinline__ float to_tf32(float x) {
    float r;
    asm("cvt.rna.tf32.f32 %0, %1;" : "=f"(r) : "f"(x));
    return r;
}

// ==================================================================================
// tf32x3 split GEMM: C = A @ B^T + bias
// A: (M,K) row-major, B: (N,K) row-major.
// BM=128, BN=128, BK=32. 256 threads = 8 warps, warp tile 32x64 (2x4 wmma 16x16x8).
// Split: A = Ah + Al, B = Bh + Bl; C ~= Ah Bh + Ah Bl + Al Bh (fp32-class accuracy).
// ==================================================================================
#define G_LDA 40
#define GEMM_SMEM_FLOATS (4 * 128 * G_LDA)
#define GEMM_SMEM_BYTES  (GEMM_SMEM_FLOATS * sizeof(float))

__global__ __launch_bounds__(256, 1)
void gemm_tf32x3_kernel(const float* __restrict__ A, const float* __restrict__ B,
                        const float* __restrict__ bias, float* __restrict__ C,
                        int M, int N, int K)
{
    extern __shared__ float sm[];
    float* Ah = sm;
    float* Al = Ah + 128 * G_LDA;
    float* Bh = Al + 128 * G_LDA;
    float* Bl = Bh + 128 * G_LDA;
    __shared__ float stage[8][256];

    const int tid  = threadIdx.x;
    const int warp = tid >> 5;
    const int lane = tid & 31;
    const int wm = warp & 3;   // 4 warps along M (32 rows each)
    const int wn = warp >> 2;  // 2 warps along N (64 cols each)

    const int m0 = blockIdx.y * 128;
    const int n0 = blockIdx.x * 128;

    wmma::fragment<wmma::accumulator, 16, 16, 8, float> c[2][4];
#pragma unroll
    for (int i = 0; i < 2; i++)
#pragma unroll
        for (int j = 0; j < 4; j++) wmma::fill_fragment(c[i][j], 0.0f);

    for (int k0 = 0; k0 < K; k0 += 32) {
        // ---- load + split A,B tiles ----
#pragma unroll
        for (int rep = 0; rep < 4; rep++) {
            const int idx = rep * 256 + tid;
            const int row = idx >> 3;
            const int c4  = (idx & 7) << 2;
            float4 va = *(const float4*)(A + (size_t)(m0 + row) * K + k0 + c4);
            float hx = to_tf32(va.x), hy = to_tf32(va.y), hz = to_tf32(va.z), hw = to_tf32(va.w);
            Ah[row * G_LDA + c4 + 0] = hx;
            Ah[row * G_LDA + c4 + 1] = hy;
            Ah[row * G_LDA + c4 + 2] = hz;
            Ah[row * G_LDA + c4 + 3] = hw;
            Al[row * G_LDA + c4 + 0] = to_tf32(va.x - hx);
            Al[row * G_LDA + c4 + 1] = to_tf32(va.y - hy);
            Al[row * G_LDA + c4 + 2] = to_tf32(va.z - hz);
            Al[row * G_LDA + c4 + 3] = to_tf32(va.w - hw);

            float4 vb = *(const float4*)(B + (size_t)(n0 + row) * K + k0 + c4);
            hx = to_tf32(vb.x); hy = to_tf32(vb.y); hz = to_tf32(vb.z); hw = to_tf32(vb.w);
            Bh[row * G_LDA + c4 + 0] = hx;
            Bh[row * G_LDA + c4 + 1] = hy;
            Bh[row * G_LDA + c4 + 2] = hz;
            Bh[row * G_LDA + c4 + 3] = hw;
            Bl[row * G_LDA + c4 + 0] = to_tf32(vb.x - hx);
            Bl[row * G_LDA + c4 + 1] = to_tf32(vb.y - hy);
            Bl[row * G_LDA + c4 + 2] = to_tf32(vb.z - hz);
            Bl[row * G_LDA + c4 + 3] = to_tf32(vb.w - hw);
        }
        __syncthreads();

#pragma unroll
        for (int ks = 0; ks < 32; ks += 8) {
            wmma::fragment<wmma::matrix_a, 16, 16, 8, wmma::precision::tf32, wmma::row_major> ah[2], al[2];
            wmma::fragment<wmma::matrix_b, 16, 16, 8, wmma::precision::tf32, wmma::col_major> bh[4], bl[4];
#pragma unroll
            for (int i = 0; i < 2; i++) {
                wmma::load_matrix_sync(ah[i], Ah + (wm * 32 + i * 16) * G_LDA + ks, G_LDA);
                wmma::load_matrix_sync(al[i], Al + (wm * 32 + i * 16) * G_LDA + ks, G_LDA);
            }
#pragma unroll
            for (int j = 0; j < 4; j++) {
                wmma::load_matrix_sync(bh[j], Bh + (wn * 64 + j * 16) * G_LDA + ks, G_LDA);
                wmma::load_matrix_sync(bl[j], Bl + (wn * 64 + j * 16) * G_LDA + ks, G_LDA);
            }
#pragma unroll
            for (int i = 0; i < 2; i++)
#pragma unroll
                for (int j = 0; j < 4; j++) {
                    wmma::mma_sync(c[i][j], ah[i], bh[j], c[i][j]);
                    wmma::mma_sync(c[i][j], ah[i], bl[j], c[i][j]);
                    wmma::mma_sync(c[i][j], al[i], bh[j], c[i][j]);
                }
        }
        __syncthreads();
    }

    // ---- epilogue: stage per-warp, add bias, write ----
#pragma unroll
    for (int i = 0; i < 2; i++)
#pragma unroll
        for (int j = 0; j < 4; j++) {
            wmma::store_matrix_sync(stage[warp], c[i][j], 16, wmma::mem_row_major);
            __syncwarp();
#pragma unroll
            for (int e = 0; e < 8; e++) {
                const int idx = e * 32 + lane;
                const int r  = idx >> 4;
                const int cc = idx & 15;
                const int nn = n0 + wn * 64 + j * 16 + cc;
                float v = stage[warp][r * 16 + cc];
                if (bias) v += bias[nn];
                C[(size_t)(m0 + wm * 32 + i * 16 + r) * N + nn] = v;
            }
            __syncwarp();
        }
}

// ==================================================================================
// Flash attention, tf32 WMMA.
// grid = (S/64, B*H), block = 256 (8 warps).
// Q tile 64x64 resident; loop 64-row K/V tiles; scores & PV via wmma (16x16x8),
// fp32 online softmax with additive bias; O in per-thread registers.
// ==================================================================================
#define A_LD 72
#define ATTN_SMEM_FLOATS (5 * 64 * A_LD)
#define ATTN_SMEM_BYTES  (ATTN_SMEM_FLOATS * sizeof(float))

__global__ __launch_bounds__(256, 1)
void attn_tf32_kernel(const float* __restrict__ Q, const float* __restrict__ K,
                      const float* __restrict__ V, const float* __restrict__ bias,
                      float* __restrict__ O)
{
    extern __shared__ float sm[];
    float* sQ  = sm;
    float* sK  = sQ  + 64 * A_LD;
    float* sV  = sK  + 64 * A_LD;
    float* sS  = sV  + 64 * A_LD;
    float* sPV = sS  + 64 * A_LD;

    const int bh = blockIdx.y;
    const int b = bh / HEADS;
    const int h = bh % HEADS;
    const int q0 = blockIdx.x * 64;

    const int tid  = threadIdx.x;
    const int warp = tid >> 5;

    // wmma tile mapping: 64x64 output = 4x4 tiles of 16x16; warp owns 2 tiles.
    const int t0 = warp * 2;
    const int tm  = t0 >> 2;          // row tile (same for both)
    const int tn0 = t0 & 3;
    const int tn1 = tn0 + 1;

    // softmax / O-update mapping: 4 threads per row
    const int row = tid >> 2;         // 0..63
    const int cg  = tid & 3;          // col group: 16 cols each
    const int ccol = cg * 16;

    const float scale = 0.125f;       // 1/sqrt(64)

    // ---- load Q tile (scaled, tf32) ----
    const float* Qbase = Q + ((size_t)(b * SEQ + q0)) * EMB + h * HDIM;
    for (int idx = tid; idx < 64 * 16; idx += 256) {
        const int r  = idx >> 4;
        const int c4 = (idx & 15) << 2;
        float4 v = *(const float4*)(Qbase + (size_t)r * EMB + c4);
        sQ[r * A_LD + c4 + 0] = to_tf32(v.x * scale);
        sQ[r * A_LD + c4 + 1] = to_tf32(v.y * scale);
        sQ[r * A_LD + c4 + 2] = to_tf32(v.z * scale);
        sQ[r * A_LD + c4 + 3] = to_tf32(v.w * scale);
    }

    float m_i = -INFINITY, l_i = 0.0f;
    float o[16];
#pragma unroll
    for (int j = 0; j < 16; j++) o[j] = 0.0f;

    const float* biasrow = bias + ((size_t)h * SEQ + q0 + row) * SEQ;

    for (int kt = 0; kt < SEQ / 64; kt++) {
        const int k0 = kt * 64;
        __syncthreads();   // previous iteration fully consumed smem

        // ---- load K & V tiles (tf32) ----
        const float* Kbase = K + ((size_t)(b * SEQ + k0)) * EMB + h * HDIM;
        const float* Vbase = V + ((size_t)(b * SEQ + k0)) * EMB + h * HDIM;
        for (int idx = tid; idx < 64 * 16; idx += 256) {
            const int r  = idx >> 4;
            const int c4 = (idx & 15) << 2;
            float4 kv = *(const float4*)(Kbase + (size_t)r * EMB + c4);
            sK[r * A_LD + c4 + 0] = to_tf32(kv.x);
            sK[r * A_LD + c4 + 1] = to_tf32(kv.y);
            sK[r * A_LD + c4 + 2] = to_tf32(kv.z);
            sK[r * A_LD + c4 + 3] = to_tf32(kv.w);
            float4 vv = *(const float4*)(Vbase + (size_t)r * EMB + c4);
            sV[r * A_LD + c4 + 0] = to_tf32(vv.x);
            sV[r * A_LD + c4 + 1] = to_tf32(vv.y);
            sV[r * A_LD + c4 + 2] = to_tf32(vv.z);
            sV[r * A_LD + c4 + 3] = to_tf32(vv.w);
        }
        __syncthreads();

        // ---- S = Q @ K^T via wmma ----
        {
            wmma::fragment<wmma::accumulator, 16, 16, 8, float> c0, c1;
            wmma::fill_fragment(c0, 0.0f);
            wmma::fill_fragment(c1, 0.0f);
#pragma unroll
            for (int kk = 0; kk < 64; kk += 8) {
                wmma::fragment<wmma::matrix_a, 16, 16, 8, wmma::precision::tf32, wmma::row_major> af;
                wmma::fragment<wmma::matrix_b, 16, 16, 8, wmma::precision::tf32, wmma::col_major> b0, b1;
                wmma::load_matrix_sync(af, sQ + tm * 16 * A_LD + kk, A_LD);
                wmma::load_matrix_sync(b0, sK + tn0 * 16 * A_LD + kk, A_LD);
                wmma::load_matrix_sync(b1, sK + tn1 * 16 * A_LD + kk, A_LD);
                wmma::mma_sync(c0, af, b0, c0);
                wmma::mma_sync(c1, af, b1, c1);
            }
            wmma::store_matrix_sync(sS + tm * 16 * A_LD + tn0 * 16, c0, A_LD, wmma::mem_row_major);
            wmma::store_matrix_sync(sS + tm * 16 * A_LD + tn1 * 16, c1, A_LD, wmma::mem_row_major);
        }
        __syncthreads();

        // ---- softmax (4 threads per row, 16 cols each) ----
        float sv[16];
        {
            const float* brow = biasrow + k0 + ccol;
#pragma unroll
            for (int j4 = 0; j4 < 16; j4 += 4) {
                float4 bv = *(const float4*)(brow + j4);
                sv[j4 + 0] = sS[row * A_LD + ccol + j4 + 0] + bv.x;
                sv[j4 + 1] = sS[row * A_LD + ccol + j4 + 1] + bv.y;
                sv[j4 + 2] = sS[row * A_LD + ccol + j4 + 2] + bv.z;
                sv[j4 + 3] = sS[row * A_LD + ccol + j4 + 3] + bv.w;
            }
            float t = sv[0];
#pragma unroll
            for (int j = 1; j < 16; j++) t = fmaxf(t, sv[j]);
            t = fmaxf(t, __shfl_xor_sync(0xffffffffu, t, 1));
            t = fmaxf(t, __shfl_xor_sync(0xffffffffu, t, 2));
            const float mnew = fmaxf(m_i, t);
            const float alpha = __expf(m_i - mnew);
            float rs = 0.0f;
#pragma unroll
            for (int j = 0; j < 16; j++) {
                sv[j] = __expf(sv[j] - mnew);
                rs += sv[j];
            }
            rs += __shfl_xor_sync(0xffffffffu, rs, 1);
            rs += __shfl_xor_sync(0xffffffffu, rs, 2);
            l_i = l_i * alpha + rs;
            m_i = mnew;
#pragma unroll
            for (int j = 0; j < 16; j++) {
                o[j] *= alpha;
                sS[row * A_LD + ccol + j] = to_tf32(sv[j]);
            }
        }
        __syncthreads();

        // ---- PV = P @ V via wmma ----
        {
            wmma::fragment<wmma::accumulator, 16, 16, 8, float> d0, d1;
            wmma::fill_fragment(d0, 0.0f);
            wmma::fill_fragment(d1, 0.0f);
#pragma unroll
            for (int kk = 0; kk < 64; kk += 8) {
                wmma::fragment<wmma::matrix_a, 16, 16, 8, wmma::precision::tf32, wmma::row_major> pf;
                wmma::fragment<wmma::matrix_b, 16, 16, 8, wmma::precision::tf32, wmma::row_major> v0, v1;
                wmma::load_matrix_sync(pf, sS + tm * 16 * A_LD + kk, A_LD);
                wmma::load_matrix_sync(v0, sV + kk * A_LD + tn0 * 16, A_LD);
                wmma::load_matrix_sync(v1, sV + kk * A_LD + tn1 * 16, A_LD);
                wmma::mma_sync(d0, pf, v0, d0);
                wmma::mma_sync(d1, pf, v1, d1);
            }
            wmma::store_matrix_sync(sPV + tm * 16 * A_LD + tn0 * 16, d0, A_LD, wmma::mem_row_major);
            wmma::store_matrix_sync(sPV + tm * 16 * A_LD + tn1 * 16, d1, A_LD, wmma::mem_row_major);
        }
        __syncthreads();

        // ---- O accumulate ----
#pragma unroll
        for (int j = 0; j < 16; j++)
            o[j] += sPV[row * A_LD + ccol + j];
    }

    // ---- normalize + write (B, S, H*D) ----
    const float inv = 1.0f / l_i;
    float* Obase = O + ((size_t)(b * SEQ + q0 + row)) * EMB + h * HDIM + ccol;
#pragma unroll
    for (int j4 = 0; j4 < 16; j4 += 4) {
        float4 v;
        v.x = o[j4 + 0] * inv;
        v.y = o[j4 + 1] * inv;
        v.z = o[j4 + 2] * inv;
        v.w = o[j4 + 3] * inv;
        *(float4*)(Obase + j4) = v;
    }
}

// ==================================================================================
// Launch
// ==================================================================================
extern "C" void kernel_launch(void* const* d_in, const int* in_sizes, int n_in,
                              void* d_out, int out_size)
{
    const float* X    = (const float*)d_in[0];
    const float* bias = (const float*)d_in[1];
    const float* Wq   = (const float*)d_in[2];
    const float* bq   = (const float*)d_in[3];
    const float* Wk   = (const float*)d_in[4];
    const float* bk   = (const float*)d_in[5];
    const float* Wv   = (const float*)d_in[6];
    const float* bv   = (const float*)d_in[7];
    const float* Wo   = (const float*)d_in[8];
    float* out = (float*)d_out;

    float *Qp, *Kp, *Vp, *Op;
    cudaGetSymbolAddress((void**)&Qp, g_Q);
    cudaGetSymbolAddress((void**)&Kp, g_K);
    cudaGetSymbolAddress((void**)&Vp, g_V);
    cudaGetSymbolAddress((void**)&Op, g_O);

    cudaFuncSetAttribute(gemm_tf32x3_kernel,
                         cudaFuncAttributeMaxDynamicSharedMemorySize, GEMM_SMEM_BYTES);
    cudaFuncSetAttribute(attn_tf32_kernel,
                         cudaFuncAttributeMaxDynamicSharedMemorySize, ATTN_SMEM_BYTES);

    dim3 ggrid(EMB / 128, ROWS / 128);  // (8, 32)
    gemm_tf32x3_kernel<<<ggrid, 256, GEMM_SMEM_BYTES>>>(X, Wq, bq, Qp, ROWS, EMB, EMB);
    gemm_tf32x3_kernel<<<ggrid, 256, GEMM_SMEM_BYTES>>>(X, Wk, bk, Kp, ROWS, EMB, EMB);
    gemm_tf32x3_kernel<<<ggrid, 256, GEMM_SMEM_BYTES>>>(X, Wv, bv, Vp, ROWS, EMB, EMB);

    dim3 agrid(SEQ / 64, BATCH * HEADS);  // (32, 32)
    attn_tf32_kernel<<<agrid, 256, ATTN_SMEM_BYTES>>>(Qp, Kp, Vp, bias, Op);

    gemm_tf32x3_kernel<<<ggrid, 256, GEMM_SMEM_BYTES>>>(Op, Wo, nullptr, out, ROWS, EMB, EMB);
}

// round 5
// speedup vs baseline: 2.7835x; 2.7835x over previous
#include <cuda_runtime.h>
#include <cuda_bf16.h>
#include <mma.h>
#include <math.h>

using namespace nvcuda;

// Problem constants
#define BATCH 2
#define SEQ   2048
#define EMB   1024
#define HEADS 16
#define HDIM  64
#define ROWS  (BATCH * SEQ)   // 4096

// -------------------- scratch (allocation-free: device globals) --------------------
__device__ float g_Q[ROWS * EMB];
__device__ float g_K[ROWS * EMB];
__device__ float g_V[ROWS * EMB];
__device__ float g_O[ROWS * EMB];

__device__ __forceinline__ float to_tf32(float x) {
    float r;
    asm("cvt.rna.tf32.f32 %0, %1;" : "=f"(r) : "f"(x));
    return r;
}

// ==================================================================================
// Plain tf32 GEMM: C = A @ B^T (+ bias)
// A: (M,K) row-major, B: (N,K) row-major.
// BM=128, BN=128, BK=32, 256 threads = 8 warps, warp tile 32x64 (2x4 wmma 16x16x8).
// ==================================================================================
#define G_LDA 40
#define GEMM_SMEM_FLOATS (2 * 128 * G_LDA)
#define GEMM_SMEM_BYTES  (GEMM_SMEM_FLOATS * sizeof(float))

__device__ __forceinline__
void gemm_tf32_body(const float* __restrict__ A, const float* __restrict__ B,
                    const float* __restrict__ bias, float* __restrict__ C,
                    int M, int N, int K, int m0, int n0, float* sm)
{
    float* As = sm;
    float* Bs = As + 128 * G_LDA;
    __shared__ float stage[8][256];

    const int tid  = threadIdx.x;
    const int warp = tid >> 5;
    const int lane = tid & 31;
    const int wm = warp & 3;   // 4 warps along M (32 rows each)
    const int wn = warp >> 2;  // 2 warps along N (64 cols each)

    wmma::fragment<wmma::accumulator, 16, 16, 8, float> c[2][4];
#pragma unroll
    for (int i = 0; i < 2; i++)
#pragma unroll
        for (int j = 0; j < 4; j++) wmma::fill_fragment(c[i][j], 0.0f);

    for (int k0 = 0; k0 < K; k0 += 32) {
#pragma unroll
        for (int rep = 0; rep < 4; rep++) {
            const int idx = rep * 256 + tid;
            const int row = idx >> 3;
            const int c4  = (idx & 7) << 2;
            float4 va = *(const float4*)(A + (size_t)(m0 + row) * K + k0 + c4);
            As[row * G_LDA + c4 + 0] = to_tf32(va.x);
            As[row * G_LDA + c4 + 1] = to_tf32(va.y);
            As[row * G_LDA + c4 + 2] = to_tf32(va.z);
            As[row * G_LDA + c4 + 3] = to_tf32(va.w);
            float4 vb = *(const float4*)(B + (size_t)(n0 + row) * K + k0 + c4);
            Bs[row * G_LDA + c4 + 0] = to_tf32(vb.x);
            Bs[row * G_LDA + c4 + 1] = to_tf32(vb.y);
            Bs[row * G_LDA + c4 + 2] = to_tf32(vb.z);
            Bs[row * G_LDA + c4 + 3] = to_tf32(vb.w);
        }
        __syncthreads();

#pragma unroll
        for (int ks = 0; ks < 32; ks += 8) {
            wmma::fragment<wmma::matrix_a, 16, 16, 8, wmma::precision::tf32, wmma::row_major> af[2];
            wmma::fragment<wmma::matrix_b, 16, 16, 8, wmma::precision::tf32, wmma::col_major> bf[4];
#pragma unroll
            for (int i = 0; i < 2; i++)
                wmma::load_matrix_sync(af[i], As + (wm * 32 + i * 16) * G_LDA + ks, G_LDA);
#pragma unroll
            for (int j = 0; j < 4; j++)
                wmma::load_matrix_sync(bf[j], Bs + (wn * 64 + j * 16) * G_LDA + ks, G_LDA);
#pragma unroll
            for (int i = 0; i < 2; i++)
#pragma unroll
                for (int j = 0; j < 4; j++)
                    wmma::mma_sync(c[i][j], af[i], bf[j], c[i][j]);
        }
        __syncthreads();
    }

    // ---- epilogue: stage per-warp, add bias, write ----
#pragma unroll
    for (int i = 0; i < 2; i++)
#pragma unroll
        for (int j = 0; j < 4; j++) {
            wmma::store_matrix_sync(stage[warp], c[i][j], 16, wmma::mem_row_major);
            __syncwarp();
#pragma unroll
            for (int e = 0; e < 8; e++) {
                const int idx = e * 32 + lane;
                const int r  = idx >> 4;
                const int cc = idx & 15;
                const int nn = n0 + wn * 64 + j * 16 + cc;
                float v = stage[warp][r * 16 + cc];
                if (bias) v += bias[nn];
                C[(size_t)(m0 + wm * 32 + i * 16 + r) * N + nn] = v;
            }
            __syncwarp();
        }
}

// Fused Q/K/V projection: blockIdx.z selects which projection.
__global__ __launch_bounds__(256, 2)
void qkv_gemm_kernel(const float* __restrict__ X,
                     const float* __restrict__ Wq, const float* __restrict__ bq,
                     const float* __restrict__ Wk, const float* __restrict__ bk,
                     const float* __restrict__ Wv, const float* __restrict__ bv,
                     float* __restrict__ Q, float* __restrict__ K, float* __restrict__ V)
{
    extern __shared__ float sm[];
    const float* W; const float* b; float* C;
    if (blockIdx.z == 0)      { W = Wq; b = bq; C = Q; }
    else if (blockIdx.z == 1) { W = Wk; b = bk; C = K; }
    else                      { W = Wv; b = bv; C = V; }
    gemm_tf32_body(X, W, b, C, ROWS, EMB, EMB,
                   blockIdx.y * 128, blockIdx.x * 128, sm);
}

__global__ __launch_bounds__(256, 2)
void oproj_gemm_kernel(const float* __restrict__ A, const float* __restrict__ B,
                       float* __restrict__ C)
{
    extern __shared__ float sm[];
    gemm_tf32_body(A, B, nullptr, C, ROWS, EMB, EMB,
                   blockIdx.y * 128, blockIdx.x * 128, sm);
}

// ==================================================================================
// Flash attention, tf32 WMMA.
// grid = (S/64, B*H), block = 256 (8 warps), 2 CTAs/SM.
// Q tile 64x64 resident; 64-row K/V tiles; S & PV via wmma; PV result reuses sS.
// ==================================================================================
#define A_LD 72
#define ATTN_SMEM_FLOATS (4 * 64 * A_LD)
#define ATTN_SMEM_BYTES  (ATTN_SMEM_FLOATS * sizeof(float))

__global__ __launch_bounds__(256, 2)
void attn_tf32_kernel(const float* __restrict__ Q, const float* __restrict__ K,
                      const float* __restrict__ V, const float* __restrict__ bias,
                      float* __restrict__ O)
{
    extern __shared__ float sm[];
    float* sQ = sm;
    float* sK = sQ + 64 * A_LD;
    float* sV = sK + 64 * A_LD;
    float* sS = sV + 64 * A_LD;   // holds S, then P, then PV

    const int bh = blockIdx.y;
    const int b = bh / HEADS;
    const int h = bh % HEADS;
    const int q0 = blockIdx.x * 64;

    const int tid  = threadIdx.x;
    const int warp = tid >> 5;

    const int tm  = warp >> 1;           // row tile 0..3
    const int tn0 = (warp & 1) * 2;      // col tiles {0,1} or {2,3}
    const int tn1 = tn0 + 1;

    const int row  = tid >> 2;           // softmax: 4 threads per row
    const int cg   = tid & 3;
    const int ccol = cg * 16;

    const float scale = 0.125f;          // 1/sqrt(64)

    // ---- load Q tile (scaled, tf32) ----
    const float* Qbase = Q + ((size_t)(b * SEQ + q0)) * EMB + h * HDIM;
    for (int idx = tid; idx < 64 * 16; idx += 256) {
        const int r  = idx >> 4;
        const int c4 = (idx & 15) << 2;
        float4 v = *(const float4*)(Qbase + (size_t)r * EMB + c4);
        sQ[r * A_LD + c4 + 0] = to_tf32(v.x * scale);
        sQ[r * A_LD + c4 + 1] = to_tf32(v.y * scale);
        sQ[r * A_LD + c4 + 2] = to_tf32(v.z * scale);
        sQ[r * A_LD + c4 + 3] = to_tf32(v.w * scale);
    }

    float m_i = -INFINITY, l_i = 0.0f;
    float o[16];
#pragma unroll
    for (int j = 0; j < 16; j++) o[j] = 0.0f;

    const float* biasrow = bias + ((size_t)h * SEQ + q0 + row) * SEQ;

    for (int kt = 0; kt < SEQ / 64; kt++) {
        const int k0 = kt * 64;
        __syncthreads();   // previous iter's sS/sK/sV consumers done

        // ---- load K & V tiles (tf32) ----
        const float* Kbase = K + ((size_t)(b * SEQ + k0)) * EMB + h * HDIM;
        const float* Vbase = V + ((size_t)(b * SEQ + k0)) * EMB + h * HDIM;
        for (int idx = tid; idx < 64 * 16; idx += 256) {
            const int r  = idx >> 4;
            const int c4 = (idx & 15) << 2;
            float4 kv = *(const float4*)(Kbase + (size_t)r * EMB + c4);
            sK[r * A_LD + c4 + 0] = to_tf32(kv.x);
            sK[r * A_LD + c4 + 1] = to_tf32(kv.y);
            sK[r * A_LD + c4 + 2] = to_tf32(kv.z);
            sK[r * A_LD + c4 + 3] = to_tf32(kv.w);
            float4 vv = *(const float4*)(Vbase + (size_t)r * EMB + c4);
            sV[r * A_LD + c4 + 0] = to_tf32(vv.x);
            sV[r * A_LD + c4 + 1] = to_tf32(vv.y);
            sV[r * A_LD + c4 + 2] = to_tf32(vv.z);
            sV[r * A_LD + c4 + 3] = to_tf32(vv.w);
        }
        __syncthreads();

        // ---- S = Q @ K^T via wmma ----
        {
            wmma::fragment<wmma::accumulator, 16, 16, 8, float> c0, c1;
            wmma::fill_fragment(c0, 0.0f);
            wmma::fill_fragment(c1, 0.0f);
#pragma unroll
            for (int kk = 0; kk < 64; kk += 8) {
                wmma::fragment<wmma::matrix_a, 16, 16, 8, wmma::precision::tf32, wmma::row_major> af;
                wmma::fragment<wmma::matrix_b, 16, 16, 8, wmma::precision::tf32, wmma::col_major> b0, b1;
                wmma::load_matrix_sync(af, sQ + tm * 16 * A_LD + kk, A_LD);
                wmma::load_matrix_sync(b0, sK + tn0 * 16 * A_LD + kk, A_LD);
                wmma::load_matrix_sync(b1, sK + tn1 * 16 * A_LD + kk, A_LD);
                wmma::mma_sync(c0, af, b0, c0);
                wmma::mma_sync(c1, af, b1, c1);
            }
            wmma::store_matrix_sync(sS + tm * 16 * A_LD + tn0 * 16, c0, A_LD, wmma::mem_row_major);
            wmma::store_matrix_sync(sS + tm * 16 * A_LD + tn1 * 16, c1, A_LD, wmma::mem_row_major);
        }
        __syncthreads();

        // ---- softmax (4 threads per row, 16 cols each) ----
        {
            float sv[16];
            const float* brow = biasrow + k0 + ccol;
#pragma unroll
            for (int j4 = 0; j4 < 16; j4 += 4) {
                float4 bv = *(const float4*)(brow + j4);
                sv[j4 + 0] = sS[row * A_LD + ccol + j4 + 0] + bv.x;
                sv[j4 + 1] = sS[row * A_LD + ccol + j4 + 1] + bv.y;
                sv[j4 + 2] = sS[row * A_LD + ccol + j4 + 2] + bv.z;
                sv[j4 + 3] = sS[row * A_LD + ccol + j4 + 3] + bv.w;
            }
            float t = sv[0];
#pragma unroll
            for (int j = 1; j < 16; j++) t = fmaxf(t, sv[j]);
            t = fmaxf(t, __shfl_xor_sync(0xffffffffu, t, 1));
            t = fmaxf(t, __shfl_xor_sync(0xffffffffu, t, 2));
            const float mnew = fmaxf(m_i, t);
            const float alpha = __expf(m_i - mnew);
            float rs = 0.0f;
#pragma unroll
            for (int j = 0; j < 16; j++) {
                sv[j] = __expf(sv[j] - mnew);
                rs += sv[j];
            }
            rs += __shfl_xor_sync(0xffffffffu, rs, 1);
            rs += __shfl_xor_sync(0xffffffffu, rs, 2);
            l_i = l_i * alpha + rs;
            m_i = mnew;
#pragma unroll
            for (int j = 0; j < 16; j++) {
                o[j] *= alpha;
                sS[row * A_LD + ccol + j] = to_tf32(sv[j]);
            }
        }
        __syncthreads();

        // ---- PV = P @ V via wmma; result overwrites sS after read fence ----
        {
            wmma::fragment<wmma::accumulator, 16, 16, 8, float> d0, d1;
            wmma::fill_fragment(d0, 0.0f);
            wmma::fill_fragment(d1, 0.0f);
#pragma unroll
            for (int kk = 0; kk < 64; kk += 8) {
                wmma::fragment<wmma::matrix_a, 16, 16, 8, wmma::precision::tf32, wmma::row_major> pf;
                wmma::fragment<wmma::matrix_b, 16, 16, 8, wmma::precision::tf32, wmma::row_major> v0, v1;
                wmma::load_matrix_sync(pf, sS + tm * 16 * A_LD + kk, A_LD);
                wmma::load_matrix_sync(v0, sV + kk * A_LD + tn0 * 16, A_LD);
                wmma::load_matrix_sync(v1, sV + kk * A_LD + tn1 * 16, A_LD);
                wmma::mma_sync(d0, pf, v0, d0);
                wmma::mma_sync(d1, pf, v1, d1);
            }
            __syncthreads();   // everyone finished reading P from sS
            wmma::store_matrix_sync(sS + tm * 16 * A_LD + tn0 * 16, d0, A_LD, wmma::mem_row_major);
            wmma::store_matrix_sync(sS + tm * 16 * A_LD + tn1 * 16, d1, A_LD, wmma::mem_row_major);
        }
        __syncthreads();

        // ---- O accumulate ----
#pragma unroll
        for (int j = 0; j < 16; j++)
            o[j] += sS[row * A_LD + ccol + j];
    }

    // ---- normalize + write (B, S, H*D) ----
    const float inv = 1.0f / l_i;
    float* Obase = O + ((size_t)(b * SEQ + q0 + row)) * EMB + h * HDIM + ccol;
#pragma unroll
    for (int j4 = 0; j4 < 16; j4 += 4) {
        float4 v;
        v.x = o[j4 + 0] * inv;
        v.y = o[j4 + 1] * inv;
        v.z = o[j4 + 2] * inv;
        v.w = o[j4 + 3] * inv;
        *(float4*)(Obase + j4) = v;
    }
}

// ==================================================================================
// Launch
// ==================================================================================
extern "C" void kernel_launch(void* const* d_in, const int* in_sizes, int n_in,
                              void* d_out, int out_size)
{
    const float* X    = (const float*)d_in[0];
    const float* bias = (const float*)d_in[1];
    const float* Wq   = (const float*)d_in[2];
    const float* bq   = (const float*)d_in[3];
    const float* Wk   = (const float*)d_in[4];
    const float* bk   = (const float*)d_in[5];
    const float* Wv   = (const float*)d_in[6];
    const float* bv   = (const float*)d_in[7];
    const float* Wo   = (const float*)d_in[8];
    float* out = (float*)d_out;

    float *Qp, *Kp, *Vp, *Op;
    cudaGetSymbolAddress((void**)&Qp, g_Q);
    cudaGetSymbolAddress((void**)&Kp, g_K);
    cudaGetSymbolAddress((void**)&Vp, g_V);
    cudaGetSymbolAddress((void**)&Op, g_O);

    cudaFuncSetAttribute(qkv_gemm_kernel,
                         cudaFuncAttributeMaxDynamicSharedMemorySize, GEMM_SMEM_BYTES);
    cudaFuncSetAttribute(oproj_gemm_kernel,
                         cudaFuncAttributeMaxDynamicSharedMemorySize, GEMM_SMEM_BYTES);
    cudaFuncSetAttribute(attn_tf32_kernel,
                         cudaFuncAttributeMaxDynamicSharedMemorySize, ATTN_SMEM_BYTES);

    dim3 qkvgrid(EMB / 128, ROWS / 128, 3);  // (8, 32, 3)
    qkv_gemm_kernel<<<qkvgrid, 256, GEMM_SMEM_BYTES>>>(X, Wq, bq, Wk, bk, Wv, bv, Qp, Kp, Vp);

    dim3 agrid(SEQ / 64, BATCH * HEADS);     // (32, 32)
    attn_tf32_kernel<<<agrid, 256, ATTN_SMEM_BYTES>>>(Qp, Kp, Vp, bias, Op);

    dim3 ogrid(EMB / 128, ROWS / 128);       // (8, 32)
    oproj_gemm_kernel<<<ogrid, 256, GEMM_SMEM_BYTES>>>(Op, Wo, out);
}

// round 6
// speedup vs baseline: 4.2722x; 1.5348x over previous
#include <cuda_runtime.h>
#include <cuda_bf16.h>
#include <mma.h>
#include <math.h>

using namespace nvcuda;

// Problem constants
#define BATCH 2
#define SEQ   2048
#define EMB   1024
#define HEADS 16
#define HDIM  64
#define ROWS  (BATCH * SEQ)   // 4096

// -------------------- scratch (allocation-free: device globals) --------------------
__device__ float g_Q[ROWS * EMB];
__device__ float g_K[ROWS * EMB];
__device__ float g_V[ROWS * EMB];
__device__ float g_O[ROWS * EMB];

__device__ __forceinline__ float to_tf32(float x) {
    float r;
    asm("cvt.rna.tf32.f32 %0, %1;" : "=f"(r) : "f"(x));
    return r;
}
__device__ __forceinline__ unsigned to_tf32u(float x) {
    unsigned r;
    asm("cvt.rna.tf32.f32 %0, %1;" : "=r"(r) : "f"(x));
    return r;
}

// mma.sync m16n8k8 tf32: D = A*B + C  (A 16x8 row, B 8x8 col, C/D 16x8)
__device__ __forceinline__ void mma_tf32(float d[4], const unsigned a[4],
                                         const unsigned b[2], const float c[4]) {
    asm volatile(
        "mma.sync.aligned.m16n8k8.row.col.f32.tf32.tf32.f32 "
        "{%0,%1,%2,%3}, {%4,%5,%6,%7}, {%8,%9}, {%10,%11,%12,%13};"
        : "=f"(d[0]), "=f"(d[1]), "=f"(d[2]), "=f"(d[3])
        : "r"(a[0]), "r"(a[1]), "r"(a[2]), "r"(a[3]),
          "r"(b[0]), "r"(b[1]),
          "f"(c[0]), "f"(c[1]), "f"(c[2]), "f"(c[3]));
}

// ==================================================================================
// Plain tf32 GEMM: C = A @ B^T (+ bias)   [unchanged from round 5 — known good]
// ==================================================================================
#define G_LDA 40
#define GEMM_SMEM_FLOATS (2 * 128 * G_LDA)
#define GEMM_SMEM_BYTES  (GEMM_SMEM_FLOATS * sizeof(float))

__device__ __forceinline__
void gemm_tf32_body(const float* __restrict__ A, const float* __restrict__ B,
                    const float* __restrict__ bias, float* __restrict__ C,
                    int M, int N, int K, int m0, int n0, float* sm)
{
    float* As = sm;
    float* Bs = As + 128 * G_LDA;
    __shared__ float stage[8][256];

    const int tid  = threadIdx.x;
    const int warp = tid >> 5;
    const int lane = tid & 31;
    const int wm = warp & 3;
    const int wn = warp >> 2;

    wmma::fragment<wmma::accumulator, 16, 16, 8, float> c[2][4];
#pragma unroll
    for (int i = 0; i < 2; i++)
#pragma unroll
        for (int j = 0; j < 4; j++) wmma::fill_fragment(c[i][j], 0.0f);

    for (int k0 = 0; k0 < K; k0 += 32) {
#pragma unroll
        for (int rep = 0; rep < 4; rep++) {
            const int idx = rep * 256 + tid;
            const int row = idx >> 3;
            const int c4  = (idx & 7) << 2;
            float4 va = *(const float4*)(A + (size_t)(m0 + row) * K + k0 + c4);
            As[row * G_LDA + c4 + 0] = to_tf32(va.x);
            As[row * G_LDA + c4 + 1] = to_tf32(va.y);
            As[row * G_LDA + c4 + 2] = to_tf32(va.z);
            As[row * G_LDA + c4 + 3] = to_tf32(va.w);
            float4 vb = *(const float4*)(B + (size_t)(n0 + row) * K + k0 + c4);
            Bs[row * G_LDA + c4 + 0] = to_tf32(vb.x);
            Bs[row * G_LDA + c4 + 1] = to_tf32(vb.y);
            Bs[row * G_LDA + c4 + 2] = to_tf32(vb.z);
            Bs[row * G_LDA + c4 + 3] = to_tf32(vb.w);
        }
        __syncthreads();

#pragma unroll
        for (int ks = 0; ks < 32; ks += 8) {
            wmma::fragment<wmma::matrix_a, 16, 16, 8, wmma::precision::tf32, wmma::row_major> af[2];
            wmma::fragment<wmma::matrix_b, 16, 16, 8, wmma::precision::tf32, wmma::col_major> bf[4];
#pragma unroll
            for (int i = 0; i < 2; i++)
                wmma::load_matrix_sync(af[i], As + (wm * 32 + i * 16) * G_LDA + ks, G_LDA);
#pragma unroll
            for (int j = 0; j < 4; j++)
                wmma::load_matrix_sync(bf[j], Bs + (wn * 64 + j * 16) * G_LDA + ks, G_LDA);
#pragma unroll
            for (int i = 0; i < 2; i++)
#pragma unroll
                for (int j = 0; j < 4; j++)
                    wmma::mma_sync(c[i][j], af[i], bf[j], c[i][j]);
        }
        __syncthreads();
    }

#pragma unroll
    for (int i = 0; i < 2; i++)
#pragma unroll
        for (int j = 0; j < 4; j++) {
            wmma::store_matrix_sync(stage[warp], c[i][j], 16, wmma::mem_row_major);
            __syncwarp();
#pragma unroll
            for (int e = 0; e < 8; e++) {
                const int idx = e * 32 + lane;
                const int r  = idx >> 4;
                const int cc = idx & 15;
                const int nn = n0 + wn * 64 + j * 16 + cc;
                float v = stage[warp][r * 16 + cc];
                if (bias) v += bias[nn];
                C[(size_t)(m0 + wm * 32 + i * 16 + r) * N + nn] = v;
            }
            __syncwarp();
        }
}

__global__ __launch_bounds__(256, 2)
void qkv_gemm_kernel(const float* __restrict__ X,
                     const float* __restrict__ Wq, const float* __restrict__ bq,
                     const float* __restrict__ Wk, const float* __restrict__ bk,
                     const float* __restrict__ Wv, const float* __restrict__ bv,
                     float* __restrict__ Q, float* __restrict__ K, float* __restrict__ V)
{
    extern __shared__ float sm[];
    const float* W; const float* b; float* C;
    if (blockIdx.z == 0)      { W = Wq; b = bq; C = Q; }
    else if (blockIdx.z == 1) { W = Wk; b = bk; C = K; }
    else                      { W = Wv; b = bv; C = V; }
    gemm_tf32_body(X, W, b, C, ROWS, EMB, EMB,
                   blockIdx.y * 128, blockIdx.x * 128, sm);
}

__global__ __launch_bounds__(256, 2)
void oproj_gemm_kernel(const float* __restrict__ A, const float* __restrict__ B,
                       float* __restrict__ C)
{
    extern __shared__ float sm[];
    gemm_tf32_body(A, B, nullptr, C, ROWS, EMB, EMB,
                   blockIdx.y * 128, blockIdx.x * 128, sm);
}

// ==================================================================================
// Flash attention, register-resident, raw mma.sync m16n8k8 tf32.
// grid = (S/128, B*H) = (16, 32), block = 256 (8 warps), 2 CTAs/SM.
// Warp owns 16 q-rows x full 64 d / 64 score-cols. Q A-frags persistent in regs.
// Softmax + P entirely in registers (quad shuffles). Only K/V go through smem.
// ==================================================================================
#define LDK 68   // 68 % 32 == 4  -> K B-frag LDS conflict-free
#define LDV 72   // 72 % 32 == 8  -> V B-frag LDS conflict-free

__global__ __launch_bounds__(256, 2)
void attn_mma_kernel(const float* __restrict__ Q, const float* __restrict__ K,
                     const float* __restrict__ V, const float* __restrict__ bias,
                     float* __restrict__ O)
{
    __shared__ unsigned sK[64 * LDK];
    __shared__ unsigned sV[64 * LDV];

    const int bh = blockIdx.y;
    const int b = bh >> 4;
    const int h = bh & 15;
    const int q0 = blockIdx.x * 128;

    const int tid  = threadIdx.x;
    const int warp = tid >> 5;
    const int lane = tid & 31;
    const int gr = lane >> 2;   // group row 0..7
    const int j  = lane & 3;    // quad lane

    const int qr = q0 + warp * 16 + gr;       // this thread's rows: qr, qr+8
    const float scale = 0.125f;               // 1/sqrt(64)

    // ---- Q A-fragments, persistent (rows qr/qr+8, cols kk*8 + j / +4), scaled ----
    unsigned qa[8][4];
    {
        const float* Qb  = Q + ((size_t)(b * SEQ) + qr) * EMB + h * HDIM;
        const float* Qb2 = Qb + (size_t)8 * EMB;
#pragma unroll
        for (int kk = 0; kk < 8; kk++) {
            qa[kk][0] = to_tf32u(Qb [kk * 8 + j    ] * scale);
            qa[kk][1] = to_tf32u(Qb2[kk * 8 + j    ] * scale);
            qa[kk][2] = to_tf32u(Qb [kk * 8 + j + 4] * scale);
            qa[kk][3] = to_tf32u(Qb2[kk * 8 + j + 4] * scale);
        }
    }

    float o[8][4];
#pragma unroll
    for (int n = 0; n < 8; n++)
#pragma unroll
        for (int p = 0; p < 4; p++) o[n][p] = 0.0f;
    float m0 = -INFINITY, m1 = -INFINITY;
    float l0 = 0.0f, l1 = 0.0f;

    const float* brow0 = bias + ((size_t)h * SEQ + qr) * SEQ;
    const float* brow1 = brow0 + (size_t)8 * SEQ;

    for (int kt = 0; kt < SEQ / 64; kt++) {
        const int k0 = kt * 64;
        if (kt) __syncthreads();   // all warps done reading prev sK/sV

        // ---- load K/V tile (64 rows x 64 d) into smem as tf32 bits ----
        {
            const float* Kb = K + ((size_t)(b * SEQ + k0)) * EMB + h * HDIM;
            const float* Vb = V + ((size_t)(b * SEQ + k0)) * EMB + h * HDIM;
#pragma unroll
            for (int rep = 0; rep < 4; rep++) {
                const int idx = rep * 256 + tid;
                const int row = idx >> 4;
                const int c4  = (idx & 15) << 2;
                float4 kv = *(const float4*)(Kb + (size_t)row * EMB + c4);
                sK[row * LDK + c4 + 0] = to_tf32u(kv.x);
                sK[row * LDK + c4 + 1] = to_tf32u(kv.y);
                sK[row * LDK + c4 + 2] = to_tf32u(kv.z);
                sK[row * LDK + c4 + 3] = to_tf32u(kv.w);
                float4 vv = *(const float4*)(Vb + (size_t)row * EMB + c4);
                sV[row * LDV + c4 + 0] = to_tf32u(vv.x);
                sV[row * LDV + c4 + 1] = to_tf32u(vv.y);
                sV[row * LDV + c4 + 2] = to_tf32u(vv.z);
                sV[row * LDV + c4 + 3] = to_tf32u(vv.w);
            }
        }
        __syncthreads();

        // ---- S = Q @ K^T : 8 n-tiles x 8 k-steps of m16n8k8 ----
        float s[8][4];
#pragma unroll
        for (int n = 0; n < 8; n++) {
            s[n][0] = s[n][1] = s[n][2] = s[n][3] = 0.0f;
            const unsigned* kbase = sK + (n * 8 + gr) * LDK;
#pragma unroll
            for (int kk = 0; kk < 8; kk++) {
                unsigned bf[2];
                bf[0] = kbase[kk * 8 + j];
                bf[1] = kbase[kk * 8 + j + 4];
                mma_tf32(s[n], qa[kk], bf, s[n]);
            }
        }

        // ---- bias + online softmax, all in registers ----
        float tm0 = -INFINITY, tm1 = -INFINITY;
#pragma unroll
        for (int n = 0; n < 8; n++) {
            float2 b0 = *(const float2*)(brow0 + k0 + n * 8 + 2 * j);
            float2 b1 = *(const float2*)(brow1 + k0 + n * 8 + 2 * j);
            s[n][0] += b0.x; s[n][1] += b0.y;
            s[n][2] += b1.x; s[n][3] += b1.y;
            tm0 = fmaxf(tm0, fmaxf(s[n][0], s[n][1]));
            tm1 = fmaxf(tm1, fmaxf(s[n][2], s[n][3]));
        }
        tm0 = fmaxf(tm0, __shfl_xor_sync(0xffffffffu, tm0, 1));
        tm0 = fmaxf(tm0, __shfl_xor_sync(0xffffffffu, tm0, 2));
        tm1 = fmaxf(tm1, __shfl_xor_sync(0xffffffffu, tm1, 1));
        tm1 = fmaxf(tm1, __shfl_xor_sync(0xffffffffu, tm1, 2));

        const float mn0 = fmaxf(m0, tm0);
        const float mn1 = fmaxf(m1, tm1);
        const float al0 = __expf(m0 - mn0);
        const float al1 = __expf(m1 - mn1);
        float rs0 = 0.0f, rs1 = 0.0f;
#pragma unroll
        for (int n = 0; n < 8; n++) {
            s[n][0] = __expf(s[n][0] - mn0);
            s[n][1] = __expf(s[n][1] - mn0);
            s[n][2] = __expf(s[n][2] - mn1);
            s[n][3] = __expf(s[n][3] - mn1);
            rs0 += s[n][0] + s[n][1];
            rs1 += s[n][2] + s[n][3];
        }
        rs0 += __shfl_xor_sync(0xffffffffu, rs0, 1);
        rs0 += __shfl_xor_sync(0xffffffffu, rs0, 2);
        rs1 += __shfl_xor_sync(0xffffffffu, rs1, 1);
        rs1 += __shfl_xor_sync(0xffffffffu, rs1, 2);
        l0 = l0 * al0 + rs0;  m0 = mn0;
        l1 = l1 * al1 + rs1;  m1 = mn1;

#pragma unroll
        for (int n = 0; n < 8; n++) {
            o[n][0] *= al0; o[n][1] *= al0;
            o[n][2] *= al1; o[n][3] *= al1;
        }

        // ---- PV: for each score k-step, permute P (C-layout -> A-layout) via
        //      quad shuffles, then 8 d-tiles of m16n8k8 into O frags ----
        const int src1 = (lane & ~3) | (j >> 1);
        const int src2 = src1 + 2;
        const bool odd = (j & 1);
#pragma unroll
        for (int kk = 0; kk < 8; kk++) {
            float e0 = __shfl_sync(0xffffffffu, s[kk][0], src1);
            float o0 = __shfl_sync(0xffffffffu, s[kk][1], src1);
            float e1 = __shfl_sync(0xffffffffu, s[kk][2], src1);
            float o1 = __shfl_sync(0xffffffffu, s[kk][3], src1);
            float e2 = __shfl_sync(0xffffffffu, s[kk][0], src2);
            float o2 = __shfl_sync(0xffffffffu, s[kk][1], src2);
            float e3 = __shfl_sync(0xffffffffu, s[kk][2], src2);
            float o3 = __shfl_sync(0xffffffffu, s[kk][3], src2);
            unsigned pa[4];
            pa[0] = to_tf32u(odd ? o0 : e0);
            pa[1] = to_tf32u(odd ? o1 : e1);
            pa[2] = to_tf32u(odd ? o2 : e2);
            pa[3] = to_tf32u(odd ? o3 : e3);

            const unsigned* vb0 = sV + (kk * 8 + j) * LDV + gr;
            const unsigned* vb1 = vb0 + 4 * LDV;
#pragma unroll
            for (int n = 0; n < 8; n++) {
                unsigned bf[2];
                bf[0] = vb0[n * 8];
                bf[1] = vb1[n * 8];
                mma_tf32(o[n], pa, bf, o[n]);
            }
        }
    }

    // ---- normalize + write to (B, S, H*D) ----
    const float inv0 = 1.0f / l0;
    const float inv1 = 1.0f / l1;
    float* Ob  = O + ((size_t)(b * SEQ) + qr) * EMB + h * HDIM;
    float* Ob2 = Ob + (size_t)8 * EMB;
#pragma unroll
    for (int n = 0; n < 8; n++) {
        float2 v0, v1;
        v0.x = o[n][0] * inv0;  v0.y = o[n][1] * inv0;
        v1.x = o[n][2] * inv1;  v1.y = o[n][3] * inv1;
        *(float2*)(Ob  + n * 8 + 2 * j) = v0;
        *(float2*)(Ob2 + n * 8 + 2 * j) = v1;
    }
}

// ==================================================================================
// Launch
// ==================================================================================
extern "C" void kernel_launch(void* const* d_in, const int* in_sizes, int n_in,
                              void* d_out, int out_size)
{
    const float* X    = (const float*)d_in[0];
    const float* bias = (const float*)d_in[1];
    const float* Wq   = (const float*)d_in[2];
    const float* bq   = (const float*)d_in[3];
    const float* Wk   = (const float*)d_in[4];
    const float* bk   = (const float*)d_in[5];
    const float* Wv   = (const float*)d_in[6];
    const float* bv   = (const float*)d_in[7];
    const float* Wo   = (const float*)d_in[8];
    float* out = (float*)d_out;

    float *Qp, *Kp, *Vp, *Op;
    cudaGetSymbolAddress((void**)&Qp, g_Q);
    cudaGetSymbolAddress((void**)&Kp, g_K);
    cudaGetSymbolAddress((void**)&Vp, g_V);
    cudaGetSymbolAddress((void**)&Op, g_O);

    cudaFuncSetAttribute(qkv_gemm_kernel,
                         cudaFuncAttributeMaxDynamicSharedMemorySize, GEMM_SMEM_BYTES);
    cudaFuncSetAttribute(oproj_gemm_kernel,
                         cudaFuncAttributeMaxDynamicSharedMemorySize, GEMM_SMEM_BYTES);

    dim3 qkvgrid(EMB / 128, ROWS / 128, 3);  // (8, 32, 3)
    qkv_gemm_kernel<<<qkvgrid, 256, GEMM_SMEM_BYTES>>>(X, Wq, bq, Wk, bk, Wv, bv, Qp, Kp, Vp);

    dim3 agrid(SEQ / 128, BATCH * HEADS);    // (16, 32)
    attn_mma_kernel<<<agrid, 256>>>(Qp, Kp, Vp, bias, Op);

    dim3 ogrid(EMB / 128, ROWS / 128);       // (8, 32)
    oproj_gemm_kernel<<<ogrid, 256, GEMM_SMEM_BYTES>>>(Op, Wo, out);
}

// round 9
// speedup vs baseline: 4.3177x; 1.0106x over previous
#include <cuda_runtime.h>
#include <cuda_bf16.h>
#include <mma.h>
#include <math.h>

using namespace nvcuda;

// Problem constants
#define BATCH 2
#define SEQ   2048
#define EMB   1024
#define HEADS 16
#define HDIM  64
#define ROWS  (BATCH * SEQ)   // 4096

// -------------------- scratch (allocation-free: device globals) --------------------
__device__ float g_Q[ROWS * EMB];
__device__ float g_K[ROWS * EMB];
__device__ float g_V[ROWS * EMB];
__device__ float g_O[ROWS * EMB];

__device__ __forceinline__ float to_tf32(float x) {
    float r;
    asm("cvt.rna.tf32.f32 %0, %1;" : "=f"(r) : "f"(x));
    return r;
}
__device__ __forceinline__ unsigned to_tf32u(float x) {
    unsigned r;
    asm("cvt.rna.tf32.f32 %0, %1;" : "=r"(r) : "f"(x));
    return r;
}

// mma.sync m16n8k8 tf32: D = A*B + C
__device__ __forceinline__ void mma_tf32(float d[4], const unsigned a[4],
                                         const unsigned b[2], const float c[4]) {
    asm volatile(
        "mma.sync.aligned.m16n8k8.row.col.f32.tf32.tf32.f32 "
        "{%0,%1,%2,%3}, {%4,%5,%6,%7}, {%8,%9}, {%10,%11,%12,%13};"
        : "=f"(d[0]), "=f"(d[1]), "=f"(d[2]), "=f"(d[3])
        : "r"(a[0]), "r"(a[1]), "r"(a[2]), "r"(a[3]),
          "r"(b[0]), "r"(b[1]),
          "f"(c[0]), "f"(c[1]), "f"(c[2]), "f"(c[3]));
}

// cp.async helpers
__device__ __forceinline__ void cp_async16(unsigned saddr, const void* gptr) {
    asm volatile("cp.async.cg.shared.global [%0], [%1], 16;" :: "r"(saddr), "l"(gptr));
}
__device__ __forceinline__ void cp_commit() {
    asm volatile("cp.async.commit_group;");
}
__device__ __forceinline__ void cp_wait1() {
    asm volatile("cp.async.wait_group 1;");
}
__device__ __forceinline__ void cp_wait0() {
    asm volatile("cp.async.wait_group 0;");
}

// ==================================================================================
// tf32 GEMM, 2-stage cp.async pipeline: C = A @ B^T (+ bias)
// A: (M,K) row-major, B: (N,K) row-major. BM=BN=128, BK=32, 256 thr = 8 warps.
// Raw fp32 staged via cp.async; RNA tf32 rounding applied on fragment registers.
// ==================================================================================
#define G_LDA 40
#define G_STAGE_FLOATS (2 * 128 * G_LDA)                 // A+B, one stage
#define GEMM_SMEM_BYTES (2 * G_STAGE_FLOATS * 4)         // 2 stages = 81920 B

__device__ __forceinline__
void gemm_stage_load(const float* __restrict__ A, const float* __restrict__ B,
                     int K, int m0, int n0, int k0, unsigned sbase)
{
    const int tid = threadIdx.x;
#pragma unroll
    for (int rep = 0; rep < 4; rep++) {
        const int idx = rep * 256 + tid;
        const int row = idx >> 3;
        const int c4  = (idx & 7) << 2;
        const unsigned soff = (unsigned)(row * G_LDA + c4) * 4u;
        cp_async16(sbase + soff, A + (size_t)(m0 + row) * K + k0 + c4);
        cp_async16(sbase + (unsigned)(128 * G_LDA) * 4u + soff,
                   B + (size_t)(n0 + row) * K + k0 + c4);
    }
}

__device__ __forceinline__
void gemm_body(const float* __restrict__ A, const float* __restrict__ B,
               const float* __restrict__ bias, float* __restrict__ C,
               int M, int N, int K, int m0, int n0, float* sm, bool round_out)
{
    __shared__ float stage[8][256];
    const unsigned sm_u32 = (unsigned)__cvta_generic_to_shared(sm);

    const int tid  = threadIdx.x;
    const int warp = tid >> 5;
    const int lane = tid & 31;
    const int wm = warp & 3;
    const int wn = warp >> 2;

    wmma::fragment<wmma::accumulator, 16, 16, 8, float> c[2][4];
#pragma unroll
    for (int i = 0; i < 2; i++)
#pragma unroll
        for (int j = 0; j < 4; j++) wmma::fill_fragment(c[i][j], 0.0f);

    const int NT = K / 32;
    gemm_stage_load(A, B, K, m0, n0, 0, sm_u32);
    cp_commit();

    for (int t = 0; t < NT; t++) {
        if (t + 1 < NT) {
            gemm_stage_load(A, B, K, m0, n0, (t + 1) * 32,
                            sm_u32 + (unsigned)((t + 1) & 1) * G_STAGE_FLOATS * 4u);
            cp_commit();
            cp_wait1();
        } else {
            cp_wait0();
        }
        __syncthreads();

        float* As = sm + (t & 1) * G_STAGE_FLOATS;
        float* Bs = As + 128 * G_LDA;

#pragma unroll
        for (int ks = 0; ks < 32; ks += 8) {
            wmma::fragment<wmma::matrix_a, 16, 16, 8, wmma::precision::tf32, wmma::row_major> af[2];
            wmma::fragment<wmma::matrix_b, 16, 16, 8, wmma::precision::tf32, wmma::col_major> bf[4];
#pragma unroll
            for (int i = 0; i < 2; i++) {
                wmma::load_matrix_sync(af[i], As + (wm * 32 + i * 16) * G_LDA + ks, G_LDA);
#pragma unroll
                for (int e = 0; e < af[i].num_elements; e++)
                    af[i].x[e] = to_tf32(af[i].x[e]);
            }
#pragma unroll
            for (int j = 0; j < 4; j++) {
                wmma::load_matrix_sync(bf[j], Bs + (wn * 64 + j * 16) * G_LDA + ks, G_LDA);
#pragma unroll
                for (int e = 0; e < bf[j].num_elements; e++)
                    bf[j].x[e] = to_tf32(bf[j].x[e]);
            }
#pragma unroll
            for (int i = 0; i < 2; i++)
#pragma unroll
                for (int j = 0; j < 4; j++)
                    wmma::mma_sync(c[i][j], af[i], bf[j], c[i][j]);
        }
        __syncthreads();
    }

    // ---- epilogue: stage per-warp, add bias, (optionally tf32-round), write ----
#pragma unroll
    for (int i = 0; i < 2; i++)
#pragma unroll
        for (int j = 0; j < 4; j++) {
            wmma::store_matrix_sync(stage[warp], c[i][j], 16, wmma::mem_row_major);
            __syncwarp();
#pragma unroll
            for (int e = 0; e < 8; e++) {
                const int idx = e * 32 + lane;
                const int r  = idx >> 4;
                const int cc = idx & 15;
                const int nn = n0 + wn * 64 + j * 16 + cc;
                float v = stage[warp][r * 16 + cc];
                if (bias) v += bias[nn];
                if (round_out) v = to_tf32(v);
                C[(size_t)(m0 + wm * 32 + i * 16 + r) * N + nn] = v;
            }
            __syncwarp();
        }
}

// Fused Q/K/V projection: blockIdx.z selects which projection. Output pre-rounded
// to tf32 (exactly the rounding the attention kernel would apply anyway).
__global__ __launch_bounds__(256, 2)
void qkv_gemm_kernel(const float* __restrict__ X,
                     const float* __restrict__ Wq, const float* __restrict__ bq,
                     const float* __restrict__ Wk, const float* __restrict__ bk,
                     const float* __restrict__ Wv, const float* __restrict__ bv,
                     float* __restrict__ Q, float* __restrict__ K, float* __restrict__ V)
{
    extern __shared__ float sm[];
    const float* W; const float* b; float* C;
    if (blockIdx.z == 0)      { W = Wq; b = bq; C = Q; }
    else if (blockIdx.z == 1) { W = Wk; b = bk; C = K; }
    else                      { W = Wv; b = bv; C = V; }
    gemm_body(X, W, b, C, ROWS, EMB, EMB,
              blockIdx.y * 128, blockIdx.x * 128, sm, true);
}

__global__ __launch_bounds__(256, 2)
void oproj_gemm_kernel(const float* __restrict__ A, const float* __restrict__ B,
                       float* __restrict__ C)
{
    extern __shared__ float sm[];
    gemm_body(A, B, nullptr, C, ROWS, EMB, EMB,
              blockIdx.y * 128, blockIdx.x * 128, sm, false);
}

// ==================================================================================
// Flash attention, register-resident mma.sync tf32, 2-stage cp.async K/V pipeline.
// K/V in gmem are already tf32-rounded (qkv epilogue) -> zero conversion here.
// grid = (S/128, B*H) = (16, 32), block = 256 (8 warps), 2 CTAs/SM.
// ==================================================================================
#define LDK 68   // 68 % 32 == 4  -> K B-frag LDS conflict-free
#define LDV 72   // 72 % 32 == 8  -> V B-frag LDS conflict-free
#define AKV_FLOATS (64 * LDK + 64 * LDV)            // 8960 per stage
#define ATTN_SMEM_BYTES (2 * AKV_FLOATS * 4)        // 71680

__global__ __launch_bounds__(256, 2)
void attn_mma_kernel(const float* __restrict__ Q, const float* __restrict__ K,
                     const float* __restrict__ V, const float* __restrict__ bias,
                     float* __restrict__ O)
{
    extern __shared__ unsigned skv[];
    const unsigned skv_u32 = (unsigned)__cvta_generic_to_shared(skv);

    const int bh = blockIdx.y;
    const int b = bh >> 4;
    const int h = bh & 15;
    const int q0 = blockIdx.x * 128;

    const int tid  = threadIdx.x;
    const int warp = tid >> 5;
    const int lane = tid & 31;
    const int gr = lane >> 2;   // group row 0..7
    const int j  = lane & 3;    // quad lane

    const int qr = q0 + warp * 16 + gr;
    const float scale = 0.125f;

    const float* Kbase0 = K + ((size_t)(b * SEQ)) * EMB + h * HDIM;
    const float* Vbase0 = V + ((size_t)(b * SEQ)) * EMB + h * HDIM;

    // stage loader (all 256 threads; 8 cp.async each)
    auto load_kv = [&](int k0, int stg) {
        const unsigned base = skv_u32 + (unsigned)stg * AKV_FLOATS * 4u;
        const float* Kb = Kbase0 + (size_t)k0 * EMB;
        const float* Vb = Vbase0 + (size_t)k0 * EMB;
#pragma unroll
        for (int rep = 0; rep < 4; rep++) {
            const int idx = rep * 256 + tid;
            const int row = idx >> 4;
            const int c4  = (idx & 15) << 2;
            cp_async16(base + (unsigned)(row * LDK + c4) * 4u,
                       Kb + (size_t)row * EMB + c4);
            cp_async16(base + (unsigned)(64 * LDK + row * LDV + c4) * 4u,
                       Vb + (size_t)row * EMB + c4);
        }
    };

    // ---- Q A-fragments, persistent (values already tf32 in gmem; scale exact) ----
    unsigned qa[8][4];
    {
        const float* Qb  = Q + ((size_t)(b * SEQ) + qr) * EMB + h * HDIM;
        const float* Qb2 = Qb + (size_t)8 * EMB;
#pragma unroll
        for (int kk = 0; kk < 8; kk++) {
            qa[kk][0] = to_tf32u(Qb [kk * 8 + j    ] * scale);
            qa[kk][1] = to_tf32u(Qb2[kk * 8 + j    ] * scale);
            qa[kk][2] = to_tf32u(Qb [kk * 8 + j + 4] * scale);
            qa[kk][3] = to_tf32u(Qb2[kk * 8 + j + 4] * scale);
        }
    }

    float o[8][4];
#pragma unroll
    for (int n = 0; n < 8; n++)
#pragma unroll
        for (int p = 0; p < 4; p++) o[n][p] = 0.0f;
    float m0 = -INFINITY, m1 = -INFINITY;
    float l0 = 0.0f, l1 = 0.0f;

    const float* brow0 = bias + ((size_t)h * SEQ + qr) * SEQ;
    const float* brow1 = brow0 + (size_t)8 * SEQ;

    const int NT = SEQ / 64;   // 32
    load_kv(0, 0);
    cp_commit();

    for (int kt = 0; kt < NT; kt++) {
        const int k0 = kt * 64;
        if (kt + 1 < NT) {
            load_kv((kt + 1) * 64, (kt + 1) & 1);
            cp_commit();
            cp_wait1();
        } else {
            cp_wait0();
        }
        __syncthreads();

        const unsigned* sK = skv + (kt & 1) * AKV_FLOATS;
        const unsigned* sV = sK + 64 * LDK;

        // ---- S = Q @ K^T : 8 n-tiles x 8 k-steps of m16n8k8 ----
        float s[8][4];
#pragma unroll
        for (int n = 0; n < 8; n++) {
            s[n][0] = s[n][1] = s[n][2] = s[n][3] = 0.0f;
            const unsigned* kbase = sK + (n * 8 + gr) * LDK;
#pragma unroll
            for (int kk = 0; kk < 8; kk++) {
                unsigned bf[2];
                bf[0] = kbase[kk * 8 + j];
                bf[1] = kbase[kk * 8 + j + 4];
                mma_tf32(s[n], qa[kk], bf, s[n]);
            }
        }

        // ---- bias + online softmax in registers ----
        float tm0 = -INFINITY, tm1 = -INFINITY;
#pragma unroll
        for (int n = 0; n < 8; n++) {
            float2 b0 = *(const float2*)(brow0 + k0 + n * 8 + 2 * j);
            float2 b1 = *(const float2*)(brow1 + k0 + n * 8 + 2 * j);
            s[n][0] += b0.x; s[n][1] += b0.y;
            s[n][2] += b1.x; s[n][3] += b1.y;
            tm0 = fmaxf(tm0, fmaxf(s[n][0], s[n][1]));
            tm1 = fmaxf(tm1, fmaxf(s[n][2], s[n][3]));
        }
        tm0 = fmaxf(tm0, __shfl_xor_sync(0xffffffffu, tm0, 1));
        tm0 = fmaxf(tm0, __shfl_xor_sync(0xffffffffu, tm0, 2));
        tm1 = fmaxf(tm1, __shfl_xor_sync(0xffffffffu, tm1, 1));
        tm1 = fmaxf(tm1, __shfl_xor_sync(0xffffffffu, tm1, 2));

        const float mn0 = fmaxf(m0, tm0);
        const float mn1 = fmaxf(m1, tm1);
        const float al0 = __expf(m0 - mn0);
        const float al1 = __expf(m1 - mn1);
        float rs0 = 0.0f, rs1 = 0.0f;
#pragma unroll
        for (int n = 0; n < 8; n++) {
            s[n][0] = __expf(s[n][0] - mn0);
            s[n][1] = __expf(s[n][1] - mn0);
            s[n][2] = __expf(s[n][2] - mn1);
            s[n][3] = __expf(s[n][3] - mn1);
            rs0 += s[n][0] + s[n][1];
            rs1 += s[n][2] + s[n][3];
        }
        rs0 += __shfl_xor_sync(0xffffffffu, rs0, 1);
        rs0 += __shfl_xor_sync(0xffffffffu, rs0, 2);
        rs1 += __shfl_xor_sync(0xffffffffu, rs1, 1);
        rs1 += __shfl_xor_sync(0xffffffffu, rs1, 2);
        l0 = l0 * al0 + rs0;  m0 = mn0;
        l1 = l1 * al1 + rs1;  m1 = mn1;

#pragma unroll
        for (int n = 0; n < 8; n++) {
            o[n][0] *= al0; o[n][1] *= al0;
            o[n][2] *= al1; o[n][3] *= al1;
        }

        // ---- PV: C-layout -> A-layout permute in registers, then mma into O ----
        const int src1 = (lane & ~3) | (j >> 1);
        const int src2 = src1 + 2;
        const bool odd = (j & 1);
#pragma unroll
        for (int kk = 0; kk < 8; kk++) {
            float e0 = __shfl_sync(0xffffffffu, s[kk][0], src1);
            float o0 = __shfl_sync(0xffffffffu, s[kk][1], src1);
            float e1 = __shfl_sync(0xffffffffu, s[kk][2], src1);
            float o1 = __shfl_sync(0xffffffffu, s[kk][3], src1);
            float e2 = __shfl_sync(0xffffffffu, s[kk][0], src2);
            float o2 = __shfl_sync(0xffffffffu, s[kk][1], src2);
            float e3 = __shfl_sync(0xffffffffu, s[kk][2], src2);
            float o3 = __shfl_sync(0xffffffffu, s[kk][3], src2);
            unsigned pa[4];
            pa[0] = to_tf32u(odd ? o0 : e0);
            pa[1] = to_tf32u(odd ? o1 : e1);
            pa[2] = to_tf32u(odd ? o2 : e2);
            pa[3] = to_tf32u(odd ? o3 : e3);

            const unsigned* vb0 = sV + (kk * 8 + j) * LDV + gr;
            const unsigned* vb1 = vb0 + 4 * LDV;
#pragma unroll
            for (int n = 0; n < 8; n++) {
                unsigned bf[2];
                bf[0] = vb0[n * 8];
                bf[1] = vb1[n * 8];
                mma_tf32(o[n], pa, bf, o[n]);
            }
        }
        __syncthreads();   // all warps done with this stage before it is refilled
    }

    // ---- normalize + write to (B, S, H*D) ----
    const float inv0 = 1.0f / l0;
    const float inv1 = 1.0f / l1;
    float* Ob  = O + ((size_t)(b * SEQ) + qr) * EMB + h * HDIM;
    float* Ob2 = Ob + (size_t)8 * EMB;
#pragma unroll
    for (int n = 0; n < 8; n++) {
        float2 v0, v1;
        v0.x = o[n][0] * inv0;  v0.y = o[n][1] * inv0;
        v1.x = o[n][2] * inv1;  v1.y = o[n][3] * inv1;
        *(float2*)(Ob  + n * 8 + 2 * j) = v0;
        *(float2*)(Ob2 + n * 8 + 2 * j) = v1;
    }
}

// ==================================================================================
// Launch
// ==================================================================================
extern "C" void kernel_launch(void* const* d_in, const int* in_sizes, int n_in,
                              void* d_out, int out_size)
{
    const float* X    = (const float*)d_in[0];
    const float* bias = (const float*)d_in[1];
    const float* Wq   = (const float*)d_in[2];
    const float* bq   = (const float*)d_in[3];
    const float* Wk   = (const float*)d_in[4];
    const float* bk   = (const float*)d_in[5];
    const float* Wv   = (const float*)d_in[6];
    const float* bv   = (const float*)d_in[7];
    const float* Wo   = (const float*)d_in[8];
    float* out = (float*)d_out;

    float *Qp, *Kp, *Vp, *Op;
    cudaGetSymbolAddress((void**)&Qp, g_Q);
    cudaGetSymbolAddress((void**)&Kp, g_K);
    cudaGetSymbolAddress((void**)&Vp, g_V);
    cudaGetSymbolAddress((void**)&Op, g_O);

    cudaFuncSetAttribute(qkv_gemm_kernel,
                         cudaFuncAttributeMaxDynamicSharedMemorySize, GEMM_SMEM_BYTES);
    cudaFuncSetAttribute(oproj_gemm_kernel,
                         cudaFuncAttributeMaxDynamicSharedMemorySize, GEMM_SMEM_BYTES);
    cudaFuncSetAttribute(attn_mma_kernel,
                         cudaFuncAttributeMaxDynamicSharedMemorySize, ATTN_SMEM_BYTES);

    dim3 qkvgrid(EMB / 128, ROWS / 128, 3);  // (8, 32, 3)
    qkv_gemm_kernel<<<qkvgrid, 256, GEMM_SMEM_BYTES>>>(X, Wq, bq, Wk, bk, Wv, bv, Qp, Kp, Vp);

    dim3 agrid(SEQ / 128, BATCH * HEADS);    // (16, 32)
    attn_mma_kernel<<<agrid, 256, ATTN_SMEM_BYTES>>>(Qp, Kp, Vp, bias, Op);

    dim3 ogrid(EMB / 128, ROWS / 128);       // (8, 32)
    oproj_gemm_kernel<<<ogrid, 256, GEMM_SMEM_BYTES>>>(Op, Wo, out);
}

// round 14
// speedup vs baseline: 6.3200x; 1.4637x over previous
#include <cuda_runtime.h>
#include <cuda_bf16.h>
#include <math.h>
#include <stdint.h>

// Problem constants
#define BATCH 2
#define SEQ   2048
#define EMB   1024
#define HEADS 16
#define HDIM  64
#define ROWS  (BATCH * SEQ)   // 4096

// -------------------- scratch (allocation-free: device globals) --------------------
__device__ float g_Q[ROWS * EMB];
__device__ float g_K[ROWS * EMB];
__device__ float g_V[ROWS * EMB];
__device__ float g_O[ROWS * EMB];          // attention out, tf32-rounded
__device__ float g_Xr[ROWS * EMB];         // tf32-rounded X
__device__ float g_Wr[4 * EMB * EMB];      // tf32-rounded Wq,Wk,Wv,Wo

// -------------------- helpers --------------------
__device__ __forceinline__ float to_tf32(float x) {
    float r; asm("cvt.rna.tf32.f32 %0, %1;" : "=f"(r) : "f"(x)); return r;
}
__device__ __forceinline__ unsigned to_tf32u(float x) {
    unsigned r; asm("cvt.rna.tf32.f32 %0, %1;" : "=r"(r) : "f"(x)); return r;
}
__device__ __forceinline__ void mma_tf32(float d[4], const unsigned a[4],
                                         const unsigned b[2], const float c[4]) {
    asm volatile(
        "mma.sync.aligned.m16n8k8.row.col.f32.tf32.tf32.f32 "
        "{%0,%1,%2,%3}, {%4,%5,%6,%7}, {%8,%9}, {%10,%11,%12,%13};"
        : "=f"(d[0]), "=f"(d[1]), "=f"(d[2]), "=f"(d[3])
        : "r"(a[0]), "r"(a[1]), "r"(a[2]), "r"(a[3]),
          "r"(b[0]), "r"(b[1]),
          "f"(c[0]), "f"(c[1]), "f"(c[2]), "f"(c[3]));
}
__device__ __forceinline__ void cp_async16(unsigned saddr, const void* gptr) {
    asm volatile("cp.async.cg.shared.global [%0], [%1], 16;" :: "r"(saddr), "l"(gptr));
}
__device__ __forceinline__ void cp_commit() { asm volatile("cp.async.commit_group;"); }
__device__ __forceinline__ void cp_wait2()  { asm volatile("cp.async.wait_group 2;"); }
__device__ __forceinline__ void cp_wait1()  { asm volatile("cp.async.wait_group 1;"); }
__device__ __forceinline__ void cp_wait0()  { asm volatile("cp.async.wait_group 0;"); }

// ==================================================================================
// Prepass: tf32-round X and the four weight matrices (removes all in-GEMM cvt).
// grid.y: 0=X, 1..4=Wq,Wk,Wv,Wo
// ==================================================================================
__global__ __launch_bounds__(256)
void round_tf32_kernel(const float* __restrict__ X,
                       const float* __restrict__ Wq, const float* __restrict__ Wk,
                       const float* __restrict__ Wv, const float* __restrict__ Wo)
{
    const int seg = blockIdx.y;
    const float* src; float* dst; int n4;
    if (seg == 0) { src = X; dst = g_Xr; n4 = ROWS * EMB / 4; }
    else {
        src = (seg == 1) ? Wq : (seg == 2) ? Wk : (seg == 3) ? Wv : Wo;
        dst = g_Wr + (size_t)(seg - 1) * EMB * EMB;
        n4 = EMB * EMB / 4;
    }
    for (int i = blockIdx.x * 256 + threadIdx.x; i < n4; i += gridDim.x * 256) {
        float4 v = ((const float4*)src)[i];
        v.x = to_tf32(v.x); v.y = to_tf32(v.y);
        v.z = to_tf32(v.z); v.w = to_tf32(v.w);
        ((float4*)dst)[i] = v;
    }
}

// ==================================================================================
// tf32 GEMM via raw mma.sync m16n8k8: C = A @ B^T (+bias)
// A:(4096,1024) row-major (pre-rounded), B:(1024,1024) row-major (pre-rounded).
// CTA tile 128x256, BK=32, 8 warps, warp tile 64x64 (4 m16 x 8 n8).
// 3-stage cp.async pipeline. Padded smem stride 36 -> conflict-free fragment LDS.
// ==================================================================================
#define GLD 36
#define A_F (128 * GLD)                 // 4608 floats
#define B_F (256 * GLD)                 // 9216 floats
#define STAGE_F (A_F + B_F)             // 13824 floats
#define GEMM_SMEM_BYTES (3 * STAGE_F * 4)   // 165888

__device__ __forceinline__
void gemm_v3_body(const float* __restrict__ A, const float* __restrict__ B,
                  const float* __restrict__ bias, float* __restrict__ C,
                  int m0, int n0, float* sm, int round_out)
{
    const unsigned sm_u32 = (unsigned)__cvta_generic_to_shared(sm);

    const int tid  = threadIdx.x;
    const int warp = tid >> 5;
    const int lane = tid & 31;
    const int gr = lane >> 2;     // 0..7
    const int j  = lane & 3;      // 0..3
    const int wm = warp & 1;      // 2 warp-rows of 64
    const int wn = warp >> 1;     // 4 warp-cols of 64

    float c[4][8][4];
#pragma unroll
    for (int mt = 0; mt < 4; mt++)
#pragma unroll
        for (int nt = 0; nt < 8; nt++)
#pragma unroll
            for (int p = 0; p < 4; p++) c[mt][nt][p] = 0.0f;

    const int NT = EMB / 32;   // 32 k-tiles

    auto load_stage = [&](int t) {
        const unsigned sb = sm_u32 + (unsigned)(t % 3) * STAGE_F * 4u;
        const int k0 = t * 32;
        // A: 128 rows x 32 floats = 1024 x 16B
#pragma unroll
        for (int rep = 0; rep < 4; rep++) {
            const int id = rep * 256 + tid;
            const int row = id >> 3, c4 = (id & 7) << 2;
            cp_async16(sb + (unsigned)(row * GLD + c4) * 4u,
                       A + (size_t)(m0 + row) * EMB + k0 + c4);
        }
        // B: 256 rows x 32 floats = 2048 x 16B
#pragma unroll
        for (int rep = 0; rep < 8; rep++) {
            const int id = rep * 256 + tid;
            const int row = id >> 3, c4 = (id & 7) << 2;
            cp_async16(sb + (unsigned)(A_F + row * GLD + c4) * 4u,
                       B + (size_t)(n0 + row) * EMB + k0 + c4);
        }
        cp_commit();
    };

    load_stage(0);
    load_stage(1);
    load_stage(2);

    for (int t = 0; t < NT; t++) {
        const int rem = NT - 1 - t;
        if (rem >= 2) cp_wait2(); else if (rem == 1) cp_wait1(); else cp_wait0();
        __syncthreads();

        const unsigned* As = (const unsigned*)(sm + (t % 3) * STAGE_F);
        const unsigned* Bs = As + A_F;
        const unsigned* Abase = As + (wm * 64 + gr) * GLD + j;
        const unsigned* Bbase = Bs + (wn * 64 + gr) * GLD + j;

#pragma unroll
        for (int ks = 0; ks < 4; ks++) {
            unsigned a[4][4];
#pragma unroll
            for (int mt = 0; mt < 4; mt++) {
                const unsigned* ap = Abase + mt * 16 * GLD + ks * 8;
                a[mt][0] = ap[0];
                a[mt][1] = ap[8 * GLD];
                a[mt][2] = ap[4];
                a[mt][3] = ap[8 * GLD + 4];
            }
            unsigned b[8][2];
#pragma unroll
            for (int nt = 0; nt < 8; nt++) {
                const unsigned* bp = Bbase + nt * 8 * GLD + ks * 8;
                b[nt][0] = bp[0];
                b[nt][1] = bp[4];
            }
#pragma unroll
            for (int mt = 0; mt < 4; mt++)
#pragma unroll
                for (int nt = 0; nt < 8; nt++)
                    mma_tf32(c[mt][nt], a[mt], b[nt], c[mt][nt]);
        }
        __syncthreads();

        if (t + 3 < NT) load_stage(t + 3);
    }

    // ---- epilogue: direct float2 stores, bias from gmem (L2-resident) ----
#pragma unroll
    for (int mt = 0; mt < 4; mt++) {
        const int r = m0 + wm * 64 + mt * 16 + gr;
        float* C0 = C + (size_t)r * EMB + n0 + wn * 64;
        float* C1 = C0 + (size_t)8 * EMB;
#pragma unroll
        for (int nt = 0; nt < 8; nt++) {
            const int col = nt * 8 + 2 * j;
            float bx = 0.0f, by = 0.0f;
            if (bias) {
                float2 bv = *(const float2*)(bias + n0 + wn * 64 + col);
                bx = bv.x; by = bv.y;
            }
            float2 v0, v1;
            v0.x = c[mt][nt][0] + bx;  v0.y = c[mt][nt][1] + by;
            v1.x = c[mt][nt][2] + bx;  v1.y = c[mt][nt][3] + by;
            if (round_out) {
                v0.x = to_tf32(v0.x); v0.y = to_tf32(v0.y);
                v1.x = to_tf32(v1.x); v1.y = to_tf32(v1.y);
            }
            *(float2*)(C0 + col) = v0;
            *(float2*)(C1 + col) = v1;
        }
    }
}

// qkv: grid (1024/256, 4096/128, 3)
__global__ __launch_bounds__(256, 1)
void qkv_gemm_kernel(const float* __restrict__ bq, const float* __restrict__ bk,
                     const float* __restrict__ bv)
{
    extern __shared__ float sm[];
    const int z = blockIdx.z;
    const float* W = g_Wr + (size_t)z * EMB * EMB;
    const float* bias = (z == 0) ? bq : (z == 1) ? bk : bv;
    float* C = (z == 0) ? g_Q : (z == 1) ? g_K : g_V;
    gemm_v3_body(g_Xr, W, bias, C, blockIdx.y * 128, blockIdx.x * 256, sm, 1);
}

__global__ __launch_bounds__(256, 1)
void oproj_gemm_kernel(float* __restrict__ out)
{
    extern __shared__ float sm[];
    gemm_v3_body(g_O, g_Wr + (size_t)3 * EMB * EMB, nullptr, out,
                 blockIdx.y * 128, blockIdx.x * 256, sm, 0);
}

// ==================================================================================
// Flash attention, register-resident mma.sync tf32, 2-stage cp.async K/V pipeline.
// (round-9 version; epilogue writes tf32-rounded O for the cvt-free oproj)
// ==================================================================================
#define LDK 68
#define LDV 72
#define AKV_FLOATS (64 * LDK + 64 * LDV)
#define ATTN_SMEM_BYTES (2 * AKV_FLOATS * 4)

__global__ __launch_bounds__(256, 2)
void attn_mma_kernel(const float* __restrict__ Q, const float* __restrict__ K,
                     const float* __restrict__ V, const float* __restrict__ bias,
                     float* __restrict__ O)
{
    extern __shared__ unsigned skv[];
    const unsigned skv_u32 = (unsigned)__cvta_generic_to_shared(skv);

    const int bh = blockIdx.y;
    const int b = bh >> 4;
    const int h = bh & 15;
    const int q0 = blockIdx.x * 128;

    const int tid  = threadIdx.x;
    const int warp = tid >> 5;
    const int lane = tid & 31;
    const int gr = lane >> 2;
    const int j  = lane & 3;

    const int qr = q0 + warp * 16 + gr;
    const float scale = 0.125f;

    const float* Kbase0 = K + ((size_t)(b * SEQ)) * EMB + h * HDIM;
    const float* Vbase0 = V + ((size_t)(b * SEQ)) * EMB + h * HDIM;

    auto load_kv = [&](int k0, int stg) {
        const unsigned base = skv_u32 + (unsigned)stg * AKV_FLOATS * 4u;
        const float* Kb = Kbase0 + (size_t)k0 * EMB;
        const float* Vb = Vbase0 + (size_t)k0 * EMB;
#pragma unroll
        for (int rep = 0; rep < 4; rep++) {
            const int idx = rep * 256 + tid;
            const int row = idx >> 4;
            const int c4  = (idx & 15) << 2;
            cp_async16(base + (unsigned)(row * LDK + c4) * 4u, Kb + (size_t)row * EMB + c4);
            cp_async16(base + (unsigned)(64 * LDK + row * LDV + c4) * 4u, Vb + (size_t)row * EMB + c4);
        }
    };

    unsigned qa[8][4];
    {
        const float* Qb  = Q + ((size_t)(b * SEQ) + qr) * EMB + h * HDIM;
        const float* Qb2 = Qb + (size_t)8 * EMB;
#pragma unroll
        for (int kk = 0; kk < 8; kk++) {
            qa[kk][0] = to_tf32u(Qb [kk * 8 + j    ] * scale);
            qa[kk][1] = to_tf32u(Qb2[kk * 8 + j    ] * scale);
            qa[kk][2] = to_tf32u(Qb [kk * 8 + j + 4] * scale);
            qa[kk][3] = to_tf32u(Qb2[kk * 8 + j + 4] * scale);
        }
    }

    float o[8][4];
#pragma unroll
    for (int n = 0; n < 8; n++)
#pragma unroll
        for (int p = 0; p < 4; p++) o[n][p] = 0.0f;
    float m0 = -INFINITY, m1 = -INFINITY;
    float l0 = 0.0f, l1 = 0.0f;

    const float* brow0 = bias + ((size_t)h * SEQ + qr) * SEQ;
    const float* brow1 = brow0 + (size_t)8 * SEQ;

    const int NT = SEQ / 64;
    load_kv(0, 0);
    cp_commit();

    for (int kt = 0; kt < NT; kt++) {
        const int k0 = kt * 64;
        if (kt + 1 < NT) {
            load_kv((kt + 1) * 64, (kt + 1) & 1);
            cp_commit();
            cp_wait1();
        } else {
            cp_wait0();
        }
        __syncthreads();

        const unsigned* sK = skv + (kt & 1) * AKV_FLOATS;
        const unsigned* sV = sK + 64 * LDK;

        float s[8][4];
#pragma unroll
        for (int n = 0; n < 8; n++) {
            s[n][0] = s[n][1] = s[n][2] = s[n][3] = 0.0f;
            const unsigned* kbase = sK + (n * 8 + gr) * LDK;
#pragma unroll
            for (int kk = 0; kk < 8; kk++) {
                unsigned bf[2];
                bf[0] = kbase[kk * 8 + j];
                bf[1] = kbase[kk * 8 + j + 4];
                mma_tf32(s[n], qa[kk], bf, s[n]);
            }
        }

        float tm0 = -INFINITY, tm1 = -INFINITY;
#pragma unroll
        for (int n = 0; n < 8; n++) {
            float2 b0 = *(const float2*)(brow0 + k0 + n * 8 + 2 * j);
            float2 b1 = *(const float2*)(brow1 + k0 + n * 8 + 2 * j);
            s[n][0] += b0.x; s[n][1] += b0.y;
            s[n][2] += b1.x; s[n][3] += b1.y;
            tm0 = fmaxf(tm0, fmaxf(s[n][0], s[n][1]));
            tm1 = fmaxf(tm1, fmaxf(s[n][2], s[n][3]));
        }
        tm0 = fmaxf(tm0, __shfl_xor_sync(0xffffffffu, tm0, 1));
        tm0 = fmaxf(tm0, __shfl_xor_sync(0xffffffffu, tm0, 2));
        tm1 = fmaxf(tm1, __shfl_xor_sync(0xffffffffu, tm1, 1));
        tm1 = fmaxf(tm1, __shfl_xor_sync(0xffffffffu, tm1, 2));

        const float mn0 = fmaxf(m0, tm0);
        const float mn1 = fmaxf(m1, tm1);
        const float al0 = __expf(m0 - mn0);
        const float al1 = __expf(m1 - mn1);
        float rs0 = 0.0f, rs1 = 0.0f;
#pragma unroll
        for (int n = 0; n < 8; n++) {
            s[n][0] = __expf(s[n][0] - mn0);
            s[n][1] = __expf(s[n][1] - mn0);
            s[n][2] = __expf(s[n][2] - mn1);
            s[n][3] = __expf(s[n][3] - mn1);
            rs0 += s[n][0] + s[n][1];
            rs1 += s[n][2] + s[n][3];
        }
        rs0 += __shfl_xor_sync(0xffffffffu, rs0, 1);
        rs0 += __shfl_xor_sync(0xffffffffu, rs0, 2);
        rs1 += __shfl_xor_sync(0xffffffffu, rs1, 1);
        rs1 += __shfl_xor_sync(0xffffffffu, rs1, 2);
        l0 = l0 * al0 + rs0;  m0 = mn0;
        l1 = l1 * al1 + rs1;  m1 = mn1;

#pragma unroll
        for (int n = 0; n < 8; n++) {
            o[n][0] *= al0; o[n][1] *= al0;
            o[n][2] *= al1; o[n][3] *= al1;
        }

        const int src1 = (lane & ~3) | (j >> 1);
        const int src2 = src1 + 2;
        const bool odd = (j & 1);
#pragma unroll
        for (int kk = 0; kk < 8; kk++) {
            float e0 = __shfl_sync(0xffffffffu, s[kk][0], src1);
            float o0 = __shfl_sync(0xffffffffu, s[kk][1], src1);
            float e1 = __shfl_sync(0xffffffffu, s[kk][2], src1);
            float o1 = __shfl_sync(0xffffffffu, s[kk][3], src1);
            float e2 = __shfl_sync(0xffffffffu, s[kk][0], src2);
            float o2 = __shfl_sync(0xffffffffu, s[kk][1], src2);
            float e3 = __shfl_sync(0xffffffffu, s[kk][2], src2);
            float o3 = __shfl_sync(0xffffffffu, s[kk][3], src2);
            unsigned pa[4];
            pa[0] = to_tf32u(odd ? o0 : e0);
            pa[1] = to_tf32u(odd ? o1 : e1);
            pa[2] = to_tf32u(odd ? o2 : e2);
            pa[3] = to_tf32u(odd ? o3 : e3);

            const unsigned* vb0 = sV + (kk * 8 + j) * LDV + gr;
            const unsigned* vb1 = vb0 + 4 * LDV;
#pragma unroll
            for (int n = 0; n < 8; n++) {
                unsigned bf[2];
                bf[0] = vb0[n * 8];
                bf[1] = vb1[n * 8];
                mma_tf32(o[n], pa, bf, o[n]);
            }
        }
        __syncthreads();
    }

    // ---- normalize + tf32-round + write (oproj consumes without cvt) ----
    const float inv0 = 1.0f / l0;
    const float inv1 = 1.0f / l1;
    float* Ob  = O + ((size_t)(b * SEQ) + qr) * EMB + h * HDIM;
    float* Ob2 = Ob + (size_t)8 * EMB;
#pragma unroll
    for (int n = 0; n < 8; n++) {
        float2 v0, v1;
        v0.x = to_tf32(o[n][0] * inv0);  v0.y = to_tf32(o[n][1] * inv0);
        v1.x = to_tf32(o[n][2] * inv1);  v1.y = to_tf32(o[n][3] * inv1);
        *(float2*)(Ob  + n * 8 + 2 * j) = v0;
        *(float2*)(Ob2 + n * 8 + 2 * j) = v1;
    }
}

// ==================================================================================
// Launch
// ==================================================================================
extern "C" void kernel_launch(void* const* d_in, const int* in_sizes, int n_in,
                              void* d_out, int out_size)
{
    const float* X    = (const float*)d_in[0];
    const float* bias = (const float*)d_in[1];
    const float* Wq   = (const float*)d_in[2];
    const float* bq   = (const float*)d_in[3];
    const float* Wk   = (const float*)d_in[4];
    const float* bk   = (const float*)d_in[5];
    const float* Wv   = (const float*)d_in[6];
    const float* bv   = (const float*)d_in[7];
    const float* Wo   = (const float*)d_in[8];
    float* out = (float*)d_out;

    float *Qp, *Kp, *Vp, *Op;
    cudaGetSymbolAddress((void**)&Qp, g_Q);
    cudaGetSymbolAddress((void**)&Kp, g_K);
    cudaGetSymbolAddress((void**)&Vp, g_V);
    cudaGetSymbolAddress((void**)&Op, g_O);

    cudaFuncSetAttribute(qkv_gemm_kernel,
                         cudaFuncAttributeMaxDynamicSharedMemorySize, GEMM_SMEM_BYTES);
    cudaFuncSetAttribute(oproj_gemm_kernel,
                         cudaFuncAttributeMaxDynamicSharedMemorySize, GEMM_SMEM_BYTES);
    cudaFuncSetAttribute(attn_mma_kernel,
                         cudaFuncAttributeMaxDynamicSharedMemorySize, ATTN_SMEM_BYTES);

    // 1. tf32-round X and W
    dim3 rgrid(256, 5);
    round_tf32_kernel<<<rgrid, 256>>>(X, Wq, Wk, Wv, Wo);

    // 2. Q/K/V projections
    dim3 qkvgrid(EMB / 256, ROWS / 128, 3);  // (4, 32, 3)
    qkv_gemm_kernel<<<qkvgrid, 256, GEMM_SMEM_BYTES>>>(bq, bk, bv);

    // 3. attention
    dim3 agrid(SEQ / 128, BATCH * HEADS);    // (16, 32)
    attn_mma_kernel<<<agrid, 256, ATTN_SMEM_BYTES>>>(Qp, Kp, Vp, bias, Op);

    // 4. output projection
    dim3 ogrid(EMB / 256, ROWS / 128);       // (4, 32)
    oproj_gemm_kernel<<<ogrid, 256, GEMM_SMEM_BYTES>>>(out);
}